// round 8
// baseline (speedup 1.0000x reference)
#include <cuda_runtime.h>
#include <math.h>

// dims
#define E    256
#define H    128
#define NQ   8
#define QED  64
#define HYP  64
#define NA   14
#define BS   4096
#define BSG  512

// output layout: sorted_q [BS,NA,NQ] | h [BS,H] | rq [BSG,NQ]
#define OFF_SQ 0
#define OFF_H  (BS*NA*NQ)
#define OFF_RQ (OFF_H + BS*H)

// scratch: pair-interleaved weight layouts. pair index k2 packs {k=2k2, k=2k2+1}
__device__ __align__(16) float g_msm[2*H];
__device__ __align__(16) float g_fc1p[128*128*2];   // [k2=128][j=128] float2
__device__ __align__(16) float g_Wp[64*256*2];      // [k2=64][o=256]  float2
__device__ __align__(16) float g_wrzp[128*256*2];   // [k2=128][j=256] float2
__device__ __align__(16) float g_wnp[64*256*2];     // [k2=64][j=256]  float2
__device__ __align__(16) float g_qphi[BSG*NQ*H];

typedef unsigned long long u64t;
__device__ __forceinline__ u64t pk2(float a) {
    u64t r; asm("mov.b64 %0, {%1,%1};" : "=l"(r) : "f"(a)); return r;
}
__device__ __forceinline__ u64t pk2b(float a, float b) {
    u64t r; asm("mov.b64 %0, {%1,%2};" : "=l"(r) : "f"(a), "f"(b)); return r;
}
__device__ __forceinline__ void fma2(u64t& d, u64t a, u64t b) {
    asm("fma.rn.f32x2 %0, %1, %2, %3;" : "=l"(d) : "l"(a), "l"(b), "l"(d));
}
__device__ __forceinline__ float2 upk(u64t v) {
    float2 f; asm("mov.b64 {%0,%1}, %2;" : "=f"(f.x), "=f"(f.y) : "l"(v)); return f;
}
__device__ __forceinline__ float sigm(float x) {
    return __fdividef(1.f, 1.f + __expf(-x));
}

// cp.async helpers
__device__ __forceinline__ void cpa16(unsigned s, const void* g) {
    asm volatile("cp.async.cg.shared.global [%0], [%1], 16;" :: "r"(s), "l"(g));
}
__device__ __forceinline__ void cpcommit() { asm volatile("cp.async.commit_group;"); }
__device__ __forceinline__ void cpwait1()  { asm volatile("cp.async.wait_group 1;"); }
__device__ __forceinline__ void cpwait0()  { asm volatile("cp.async.wait_group 0;"); }

// ---------------------------------------------------------------------------
// weight prep (pair layouts) + msm + qphi. T=512.
// [0,64): buildW pairs ; [64,80): g_fc1p ; [80,144): g_wrzp ; [144,176): g_wnp
// 176: msm ; [177,177+1024): qphi (4 rows/block)
__global__ __launch_bounds__(512)
void k_wprep(const float* __restrict__ hyp_w1,
             const float* __restrict__ hyp_b1,
             const float* __restrict__ hyp_w2,
             const float* __restrict__ hyp_b2,
             const float* __restrict__ merger_w,
             const float* __restrict__ fc1_w,
             const float* __restrict__ gwi,
             const float* __restrict__ gwh,
             const float* __restrict__ rq,
             const float* __restrict__ phi_w,
             const float* __restrict__ phi_b,
             float* __restrict__ out) {
    int bid = blockIdx.x, t = threadIdx.x;
    if (bid < 64) {
        __shared__ float sh[HYP];
        __shared__ float2 sred[512];
        if (t < HYP) {
            float s = hyp_b1[t];
            #pragma unroll
            for (int q = 0; q < NQ; q++) s += hyp_w1[q*HYP + t];
            sh[t] = fmaxf(s, 0.f);
        }
        __syncthreads();
        int o = t & 255, fh = t >> 8;
        int i0 = bid*2, i1 = i0 + 1;
        float a0 = 0.f, a1 = 0.f;
        #pragma unroll 8
        for (int f = fh*32; f < fh*32 + 32; f++) {
            float s = sh[f];
            a0 = fmaf(s, hyp_w2[f*32768 + i0*256 + o], a0);
            a1 = fmaf(s, hyp_w2[f*32768 + i1*256 + o], a1);
        }
        sred[t] = make_float2(a0, a1);
        __syncthreads();
        if (t < 256) {
            float2 x = sred[t], y = sred[t+256];
            g_Wp[(bid*256 + o)*2]     = x.x + y.x + hyp_b2[i0*256 + o];
            g_Wp[(bid*256 + o)*2 + 1] = x.y + y.y + hyp_b2[i1*256 + o];
        }
    } else if (bid < 80) {
        int idx = (bid - 64)*512 + t;          // 0..8191 (float4 ids)
        float4 v = ((const float4*)fc1_w)[idx];
        int k = idx >> 5, j = (idx & 31)*4;
        int k2 = k >> 1, par = k & 1;
        g_fc1p[(k2*128 + j+0)*2 + par] = v.x;
        g_fc1p[(k2*128 + j+1)*2 + par] = v.y;
        g_fc1p[(k2*128 + j+2)*2 + par] = v.z;
        g_fc1p[(k2*128 + j+3)*2 + par] = v.w;
    } else if (bid < 144) {
        int idx = (bid - 80)*512 + t;          // 0..32767
        int j = idx >> 7, k2 = idx & 127;
        float2 v = (k2 < 64) ? ((const float2*)(gwi + j*128))[k2]
                             : ((const float2*)(gwh + j*128))[k2 - 64];
        ((float2*)g_wrzp)[k2*256 + j] = v;
    } else if (bid < 176) {
        int idx = (bid - 144)*512 + t;         // 0..16383
        int j = idx >> 6, k2 = idx & 63;
        float2 v = (j < 128) ? ((const float2*)(gwi + (256 + j)*128))[k2]
                             : ((const float2*)(gwh + (128 + j)*128))[k2];
        ((float2*)g_wnp)[k2*256 + j] = v;
    } else if (bid == 176) {
        if (t < H) {
            float a = merger_w[t], b = merger_w[H + t];
            float m = fmaxf(a, b);
            float e0 = expf(a - m), e1 = expf(b - m);
            float inv = 1.f / (e0 + e1);
            g_msm[t]     = e0 * inv;
            g_msm[H + t] = e1 * inv;
        }
    } else {
        __shared__ float cq[4][QED];
        int sub = t >> 7, tl = t & 127;
        int r = (bid - 177)*4 + sub;           // 0..4095
        float rqv = rq[r];
        if (tl < QED) cq[sub][tl] = cospif((float)tl * rqv);
        if (tl == 0) out[OFF_RQ + r] = rqv;
        __syncthreads();
        float acc = phi_b[tl];
        #pragma unroll 8
        for (int f = 0; f < QED; f++) acc = fmaf(cq[sub][f], phi_w[f*H + tl], acc);
        g_qphi[r*H + tl] = fmaxf(acc, 0.f);
    }
}

// ---------------------------------------------------------------------------
// fused main. T=512 (16 warps), 32 rows/block, grid 128.
// lane = row (0..31); warp w (0..15) owns cols j0 = w*8 .. j0+7 (plus +128 twin).
// smem floats: sA [128 k2][32] float2 (8192) — input pairs, later x2|h pairs
//              sX2 [64 k2][32] float2 (4096) — x pairs
//              sB 3×4096 weight tiles (12288)
#define SA_F 8192
#define SX_F 4096
#define SB_F 12288
#define SMEM_BYTES ((SA_F + SX_F + SB_F)*4)

__device__ __forceinline__ void stage16k(unsigned sbu, int bufi,
                                         const float* src, int tid) {
    unsigned d = sbu + (unsigned)(bufi*16384 + tid*16);
    const char* s = (const char*)src + tid*16;
    cpa16(d, s);
    cpa16(d + 8192, s + 8192);
}

__global__ __launch_bounds__(512, 1)
void k_main(const float* __restrict__ in, const float* __restrict__ hprev,
            const float* __restrict__ fc1_b,
            const float* __restrict__ gbi,  const float* __restrict__ gbh,
            const float* __restrict__ fc2_w, const float* __restrict__ fc2_b,
            float* __restrict__ out) {
    extern __shared__ float smem[];
    float* sA  = smem;
    float* sX2 = smem + SA_F;
    float* sB  = smem + SA_F + SX_F;
    unsigned sbu = (unsigned)__cvta_generic_to_shared(sB);

    const int tid  = threadIdx.x;
    const int lane = tid & 31;          // row
    const int w    = tid >> 5;          // 0..15
    const int j0   = w * 8;
    const int row0 = blockIdx.x * 32;

    stage16k(sbu, 0, g_fc1p, tid); cpcommit();

    // stage input pairs: sA[e2][row] = {in[row][2e2], in[row][2e2+1]}
    {
        const float4* src = (const float4*)(in + row0*E);
        #pragma unroll
        for (int i = tid; i < 2048; i += 512) {
            float4 v = src[i];
            int r = i >> 6, e4 = i & 63;
            float2* p0 = (float2*)(sA + ((e4*2)*32 + r)*2);
            float2* p1 = (float2*)(sA + ((e4*2+1)*32 + r)*2);
            *p0 = make_float2(v.x, v.y);
            *p1 = make_float2(v.z, v.w);
        }
    }

    // ======== FC1 : tiles g=0..7 (16 k2 each), width 128 ========
    u64t X[8] = {0,0,0,0,0,0,0,0};
    #pragma unroll 1
    for (int t = 0; t < 8; t++) {
        int g = t;
        const float* nsrc = (t < 7) ? (g_fc1p + (t+1)*4096) : g_Wp;
        stage16k(sbu, (g+1)%3, nsrc, tid); cpcommit();
        cpwait1();
        __syncthreads();
        const float* bw = sB + (g%3)*4096;
        #pragma unroll 4
        for (int kk = 0; kk < 16; kk++) {
            const float* wr = bw + (kk*128 + j0)*2;
            ulonglong2 w01 = *(const ulonglong2*)(wr);
            ulonglong2 w23 = *(const ulonglong2*)(wr + 4);
            ulonglong2 w45 = *(const ulonglong2*)(wr + 8);
            ulonglong2 w67 = *(const ulonglong2*)(wr + 12);
            u64t a2 = *(const u64t*)(sA + (((t*16+kk)*32) + lane)*2);
            fma2(X[0], a2, w01.x); fma2(X[1], a2, w01.y);
            fma2(X[2], a2, w23.x); fma2(X[3], a2, w23.y);
            fma2(X[4], a2, w45.x); fma2(X[5], a2, w45.y);
            fma2(X[6], a2, w67.x); fma2(X[7], a2, w67.y);
        }
    }
    // reduce + relu -> x pairs in sX2
    {
        float xv[8];
        #pragma unroll
        for (int c = 0; c < 8; c++) {
            float2 v = upk(X[c]);
            xv[c] = fmaxf(v.x + v.y + __ldg(fc1_b + j0 + c), 0.f);
        }
        #pragma unroll
        for (int p = 0; p < 4; p++)
            *(float2*)(sX2 + (((j0 >> 1) + p)*32 + lane)*2) = make_float2(xv[2*p], xv[2*p+1]);
    }
    __syncthreads();   // fc1 reads of sA done; x visible before emb

    // stage hprev pairs -> sA[64 + e2][row]
    {
        const float4* hsrc = (const float4*)(hprev + row0*H);
        #pragma unroll
        for (int i = tid; i < 1024; i += 512) {
            float4 v = hsrc[i];
            int r = i >> 5, e4 = i & 31;
            *(float2*)(sA + ((64 + e4*2)*32 + r)*2)   = make_float2(v.x, v.y);
            *(float2*)(sA + ((64 + e4*2+1)*32 + r)*2) = make_float2(v.z, v.w);
        }
    }

    // ======== EMB : tiles g=8..15 (8 k2 each), width 256 ========
    u64t P[8] = {0,0,0,0,0,0,0,0}, Q[8] = {0,0,0,0,0,0,0,0};
    #pragma unroll 1
    for (int t = 0; t < 8; t++) {
        int g = 8 + t;
        const float* nsrc = (t < 7) ? (g_Wp + (t+1)*4096) : g_wrzp;
        stage16k(sbu, (g+1)%3, nsrc, tid); cpcommit();
        cpwait1();
        __syncthreads();
        const float* bw = sB + (g%3)*4096;
        #pragma unroll
        for (int kk = 0; kk < 8; kk++) {
            const float* wr0 = bw + (kk*256 + j0)*2;
            const float* wr1 = bw + (kk*256 + 128 + j0)*2;
            ulonglong2 p01 = *(const ulonglong2*)(wr0);
            ulonglong2 p23 = *(const ulonglong2*)(wr0 + 4);
            ulonglong2 p45 = *(const ulonglong2*)(wr0 + 8);
            ulonglong2 p67 = *(const ulonglong2*)(wr0 + 12);
            ulonglong2 q01 = *(const ulonglong2*)(wr1);
            ulonglong2 q23 = *(const ulonglong2*)(wr1 + 4);
            ulonglong2 q45 = *(const ulonglong2*)(wr1 + 8);
            ulonglong2 q67 = *(const ulonglong2*)(wr1 + 12);
            u64t a2 = *(const u64t*)(sX2 + (((t*8+kk)*32) + lane)*2);
            fma2(P[0], a2, p01.x); fma2(P[1], a2, p01.y);
            fma2(P[2], a2, p23.x); fma2(P[3], a2, p23.y);
            fma2(P[4], a2, p45.x); fma2(P[5], a2, p45.y);
            fma2(P[6], a2, p67.x); fma2(P[7], a2, p67.y);
            fma2(Q[0], a2, q01.x); fma2(Q[1], a2, q01.y);
            fma2(Q[2], a2, q23.x); fma2(Q[3], a2, q23.y);
            fma2(Q[4], a2, q45.x); fma2(Q[5], a2, q45.y);
            fma2(Q[6], a2, q67.x); fma2(Q[7], a2, q67.y);
        }
    }
    // merge + relu -> x2 pairs in sA[0..63]
    {
        float xv[8];
        #pragma unroll
        for (int c = 0; c < 8; c++) {
            float2 a = upk(P[c]);
            float2 b = upk(Q[c]);
            float e0 = a.x + a.y, e1 = b.x + b.y;
            xv[c] = fmaxf(__ldg(g_msm + j0 + c)*e0 + __ldg(g_msm + H + j0 + c)*e1, 0.f);
        }
        #pragma unroll
        for (int p = 0; p < 4; p++)
            *(float2*)(sA + (((j0 >> 1) + p)*32 + lane)*2) = make_float2(xv[2*p], xv[2*p+1]);
    }

    // ======== GRU r,z : tiles g=16..31, a = [x2|h] pairs (128 k2) ========
    float rs[8], zs[8];
    {
        u64t R[8] = {0,0,0,0,0,0,0,0}, Z[8] = {0,0,0,0,0,0,0,0};
        #pragma unroll 1
        for (int t = 0; t < 16; t++) {
            int g = 16 + t;
            const float* nsrc = (t < 15) ? (g_wrzp + (t+1)*4096) : g_wnp;
            stage16k(sbu, (g+1)%3, nsrc, tid); cpcommit();
            cpwait1();
            __syncthreads();
            const float* bw = sB + (g%3)*4096;
            #pragma unroll
            for (int kk = 0; kk < 8; kk++) {
                const float* wr0 = bw + (kk*256 + j0)*2;
                const float* wr1 = bw + (kk*256 + 128 + j0)*2;
                ulonglong2 p01 = *(const ulonglong2*)(wr0);
                ulonglong2 p23 = *(const ulonglong2*)(wr0 + 4);
                ulonglong2 p45 = *(const ulonglong2*)(wr0 + 8);
                ulonglong2 p67 = *(const ulonglong2*)(wr0 + 12);
                ulonglong2 q01 = *(const ulonglong2*)(wr1);
                ulonglong2 q23 = *(const ulonglong2*)(wr1 + 4);
                ulonglong2 q45 = *(const ulonglong2*)(wr1 + 8);
                ulonglong2 q67 = *(const ulonglong2*)(wr1 + 12);
                u64t a2 = *(const u64t*)(sA + (((t*8+kk)*32) + lane)*2);
                fma2(R[0], a2, p01.x); fma2(R[1], a2, p01.y);
                fma2(R[2], a2, p23.x); fma2(R[3], a2, p23.y);
                fma2(R[4], a2, p45.x); fma2(R[5], a2, p45.y);
                fma2(R[6], a2, p67.x); fma2(R[7], a2, p67.y);
                fma2(Z[0], a2, q01.x); fma2(Z[1], a2, q01.y);
                fma2(Z[2], a2, q23.x); fma2(Z[3], a2, q23.y);
                fma2(Z[4], a2, q45.x); fma2(Z[5], a2, q45.y);
                fma2(Z[6], a2, q67.x); fma2(Z[7], a2, q67.y);
            }
        }
        #pragma unroll
        for (int c = 0; c < 8; c++) {
            float2 rv = upk(R[c]);
            float2 zv = upk(Z[c]);
            rs[c] = sigm(rv.x + rv.y + __ldg(gbi + j0 + c) + __ldg(gbh + j0 + c));
            zs[c] = sigm(zv.x + zv.y + __ldg(gbi + H + j0 + c) + __ldg(gbh + H + j0 + c));
        }
    }

    // ======== GRU n : tiles g=32..39 (8 k2), inn(a=x2) + hn(a=h) ========
    float hv[8];
    {
        u64t N[8] = {0,0,0,0,0,0,0,0}, G[8] = {0,0,0,0,0,0,0,0};
        #pragma unroll 1
        for (int t = 0; t < 8; t++) {
            int g = 32 + t;
            if (t < 7) { stage16k(sbu, (g+1)%3, g_wnp + (t+1)*4096, tid); cpcommit(); cpwait1(); }
            else cpwait0();
            __syncthreads();
            const float* bw = sB + (g%3)*4096;
            #pragma unroll
            for (int kk = 0; kk < 8; kk++) {
                const float* wr0 = bw + (kk*256 + j0)*2;
                const float* wr1 = bw + (kk*256 + 128 + j0)*2;
                ulonglong2 p01 = *(const ulonglong2*)(wr0);
                ulonglong2 p23 = *(const ulonglong2*)(wr0 + 4);
                ulonglong2 p45 = *(const ulonglong2*)(wr0 + 8);
                ulonglong2 p67 = *(const ulonglong2*)(wr0 + 12);
                ulonglong2 q01 = *(const ulonglong2*)(wr1);
                ulonglong2 q23 = *(const ulonglong2*)(wr1 + 4);
                ulonglong2 q45 = *(const ulonglong2*)(wr1 + 8);
                ulonglong2 q67 = *(const ulonglong2*)(wr1 + 12);
                u64t ax = *(const u64t*)(sA + (((t*8+kk)*32) + lane)*2);
                u64t ah = *(const u64t*)(sA + (((64 + t*8+kk)*32) + lane)*2);
                fma2(N[0], ax, p01.x); fma2(N[1], ax, p01.y);
                fma2(N[2], ax, p23.x); fma2(N[3], ax, p23.y);
                fma2(N[4], ax, p45.x); fma2(N[5], ax, p45.y);
                fma2(N[6], ax, p67.x); fma2(N[7], ax, p67.y);
                fma2(G[0], ah, q01.x); fma2(G[1], ah, q01.y);
                fma2(G[2], ah, q23.x); fma2(G[3], ah, q23.y);
                fma2(G[4], ah, q45.x); fma2(G[5], ah, q45.y);
                fma2(G[6], ah, q67.x); fma2(G[7], ah, q67.y);
            }
        }
        // finalize h
        #pragma unroll
        for (int p = 0; p < 4; p++) {
            u64t hp2 = *(const u64t*)(sA + ((64 + (j0 >> 1) + p)*32 + lane)*2);
            float2 hpv = upk(hp2);
            int c0i = 2*p, c1i = 2*p + 1;
            float2 nv0 = upk(N[c0i]); float2 gv0 = upk(G[c0i]);
            float2 nv1 = upk(N[c1i]); float2 gv1 = upk(G[c1i]);
            float in0 = nv0.x + nv0.y + __ldg(gbi + 2*H + j0 + c0i);
            float in1 = nv1.x + nv1.y + __ldg(gbi + 2*H + j0 + c1i);
            float hn0 = gv0.x + gv0.y + __ldg(gbh + 2*H + j0 + c0i);
            float hn1 = gv1.x + gv1.y + __ldg(gbh + 2*H + j0 + c1i);
            float n0 = tanhf(fmaf(rs[c0i], hn0, in0));
            float n1 = tanhf(fmaf(rs[c1i], hn1, in1));
            hv[c0i] = (1.f - zs[c0i])*n0 + zs[c0i]*hpv.x;
            hv[c1i] = (1.f - zs[c1i])*n1 + zs[c1i]*hpv.y;
        }
    }

    // ======== epilogue: fc2 + transpose + sort + h out ========
    // sB: sQ [32][129] at 0 ; ssq [32][112] at 4224 ; sH [32][129] at 7936
    // sX2: sW fc2_w padded [128][16]
    float* sQ  = sB;
    float* ssq = sB + 4224;
    float* sH  = sB + 7936;
    float* sW  = sX2;

    {   // write h into sH (no overlap with live tile buf0)
        #pragma unroll
        for (int c = 0; c < 8; c++) sH[lane*129 + j0 + c] = hv[c];
    }
    __syncthreads();   // all tile-39 reads + sH writes done

    #pragma unroll
    for (int i = tid; i < 4096; i += 512) {
        int qq = i >> 7, j = i & 127;
        sQ[qq*129 + j] = g_qphi[(row0 + qq)*H + j];
    }
    for (int i = tid; i < H*NA; i += 512) {
        int j = i / NA, na = i - j*NA;
        sW[j*16 + na] = fc2_w[i];
    }
    __syncthreads();

    if (tid < 256) {
        const int row = tid & 31;
        const int qi  = tid >> 5;
        const float* hrow = sH + row*129;
        const float* qrow = sQ + ((row >> 3)*8 + qi)*129;
        u64t acc[7];
        #pragma unroll
        for (int p = 0; p < 7; p++) acc[p] = pk2b(fc2_b[2*p], fc2_b[2*p+1]);
        #pragma unroll 4
        for (int j = 0; j < H; j++) {
            float hq = hrow[j] * qrow[j];
            u64t h2 = pk2(hq);
            const ulonglong2* wp = (const ulonglong2*)(sW + j*16);
            ulonglong2 w0 = wp[0], w1 = wp[1];
            u64t w2 = *(const u64t*)(sW + j*16 + 8);
            u64t w3 = *(const u64t*)(sW + j*16 + 10);
            u64t w4 = *(const u64t*)(sW + j*16 + 12);
            fma2(acc[0], h2, w0.x); fma2(acc[1], h2, w0.y);
            fma2(acc[2], h2, w1.x); fma2(acc[3], h2, w1.y);
            fma2(acc[4], h2, w2);   fma2(acc[5], h2, w3);
            fma2(acc[6], h2, w4);
        }
        #pragma unroll
        for (int p = 0; p < 7; p++) {
            float2 v = upk(acc[p]);
            ssq[row*112 + (2*p)*8   + qi] = v.x;
            ssq[row*112 + (2*p+1)*8 + qi] = v.y;
        }
    }
    __syncthreads();

    // sort: 448 (row,na) pairs ; coalesced h out
    if (tid < 448) {
        int r = tid / NA, na = tid - r*NA;
        const float* s = ssq + r*112 + na*8;
        float v[NQ];
        #pragma unroll
        for (int k = 0; k < NQ; k++) v[k] = s[k];
        #pragma unroll
        for (int i = 1; i < NQ; i++) {
            float key = v[i];
            int q = i - 1;
            while (q >= 0 && v[q] > key) { v[q+1] = v[q]; q--; }
            v[q+1] = key;
        }
        float* o = out + OFF_SQ + (row0 + r)*112 + na*8;
        *(float4*)o       = make_float4(v[0], v[1], v[2], v[3]);
        *(float4*)(o + 4) = make_float4(v[4], v[5], v[6], v[7]);
    }
    #pragma unroll
    for (int i = tid; i < 4096; i += 512)
        out[OFF_H + row0*H + i] = sH[(i >> 7)*129 + (i & 127)];
}

// ---------------------------------------------------------------------------
extern "C" void kernel_launch(void* const* d_in, const int* in_sizes, int n_in,
                              void* d_out, int out_size) {
    const float* in        = (const float*)d_in[0];
    const float* hidden    = (const float*)d_in[1];
    const float* rqs       = (const float*)d_in[2];
    const float* fc1_w     = (const float*)d_in[3];
    const float* fc1_b     = (const float*)d_in[4];
    const float* hyp_w1    = (const float*)d_in[5];
    const float* hyp_b1    = (const float*)d_in[6];
    const float* hyp_w2    = (const float*)d_in[7];
    const float* hyp_b2    = (const float*)d_in[8];
    const float* merger_w  = (const float*)d_in[9];
    const float* gru_wi    = (const float*)d_in[10];
    const float* gru_wh    = (const float*)d_in[11];
    const float* gru_bi    = (const float*)d_in[12];
    const float* gru_bh    = (const float*)d_in[13];
    const float* phi_w     = (const float*)d_in[14];
    const float* phi_b     = (const float*)d_in[15];
    const float* fc2_w     = (const float*)d_in[16];
    const float* fc2_b     = (const float*)d_in[17];
    float* out = (float*)d_out;

    static int smem_set = 0;
    if (!smem_set) {
        cudaFuncSetAttribute(k_main, cudaFuncAttributeMaxDynamicSharedMemorySize,
                             SMEM_BYTES);
        smem_set = 1;
    }

    k_wprep<<<177 + 1024, 512>>>(hyp_w1, hyp_b1, hyp_w2, hyp_b2, merger_w,
                                 fc1_w, gru_wi, gru_wh, rqs, phi_w, phi_b, out);
    k_main<<<BS/32, 512, SMEM_BYTES>>>(in, hidden, fc1_b, gru_bi, gru_bh,
                                       fc2_w, fc2_b, out);
}

// round 9
// speedup vs baseline: 1.2665x; 1.2665x over previous
#include <cuda_runtime.h>
#include <math.h>

// dims
#define E    256
#define H    128
#define NQ   8
#define QED  64
#define HYP  64
#define NA   14
#define BS   4096
#define BSG  512
#define WSZ  32768

// output layout: sorted_q [BS,NA,NQ] | h [BS,H] | rq [BSG,NQ]
#define OFF_SQ 0
#define OFF_H  (BS*NA*NQ)
#define OFF_RQ (OFF_H + BS*H)

// scratch
__device__ __align__(16) float g_msm[2*H];
__device__ __align__(16) float g_W[H*2*H];        // [128][256]
__device__ __align__(16) float g_wrz[2*H*2*H];    // [256][256]
__device__ __align__(16) float g_wn[H*2*H];       // [128][256]
__device__ __align__(16) float g_qphi[BSG*NQ*H];

typedef unsigned long long u64t;
__device__ __forceinline__ u64t pk2(float a) {
    u64t r; asm("mov.b64 %0, {%1,%1};" : "=l"(r) : "f"(a)); return r;
}
__device__ __forceinline__ u64t pk2b(float a, float b) {
    u64t r; asm("mov.b64 %0, {%1,%2};" : "=l"(r) : "f"(a), "f"(b)); return r;
}
__device__ __forceinline__ void fma2(u64t& d, u64t a, u64t b) {
    asm("fma.rn.f32x2 %0, %1, %2, %3;" : "=l"(d) : "l"(a), "l"(b), "l"(d));
}
__device__ __forceinline__ float2 upk(u64t v) {
    float2 f; asm("mov.b64 {%0,%1}, %2;" : "=f"(f.x), "=f"(f.y) : "l"(v)); return f;
}
__device__ __forceinline__ float sigm(float x) {
    return __fdividef(1.f, 1.f + __expf(-x));
}

// cp.async helpers
__device__ __forceinline__ void cpa16(unsigned s, const void* g) {
    asm volatile("cp.async.cg.shared.global [%0], [%1], 16;" :: "r"(s), "l"(g));
}
__device__ __forceinline__ void cpcommit() { asm volatile("cp.async.commit_group;"); }
__device__ __forceinline__ void cpwait1()  { asm volatile("cp.async.wait_group 1;"); }
__device__ __forceinline__ void cpwait0()  { asm volatile("cp.async.wait_group 0;"); }

// ---------------------------------------------------------------------------
// merged weight-prep + qphi kernel (proven R6 version). 256 threads/block.
__global__ __launch_bounds__(256)
void k_wprep(const float* __restrict__ hyp_w1,
             const float* __restrict__ hyp_b1,
             const float* __restrict__ hyp_w2,
             const float* __restrict__ hyp_b2,
             const float* __restrict__ merger_w,
             const float* __restrict__ gwi,
             const float* __restrict__ gwh,
             const float* __restrict__ rq,
             const float* __restrict__ phi_w,
             const float* __restrict__ phi_b,
             float* __restrict__ out) {
    int bid = blockIdx.x, t = threadIdx.x;
    if (bid < 128) {
        __shared__ float sh[HYP];
        __shared__ float4 sred[256];
        if (t < HYP) {
            float s = hyp_b1[t];
            #pragma unroll
            for (int q = 0; q < NQ; q++) s += hyp_w1[q*HYP + t];
            sh[t] = fmaxf(s, 0.f);
        }
        __syncthreads();
        int m4loc = t & 63, fc = t >> 6;
        int m4 = bid*64 + m4loc;
        const float4* src = (const float4*)hyp_w2;
        float4 acc = make_float4(0.f, 0.f, 0.f, 0.f);
        #pragma unroll
        for (int f = 0; f < 16; f++) {
            float s = sh[fc*16 + f];
            float4 v = src[(fc*16 + f)*8192 + m4];
            acc.x = fmaf(s, v.x, acc.x);
            acc.y = fmaf(s, v.y, acc.y);
            acc.z = fmaf(s, v.z, acc.z);
            acc.w = fmaf(s, v.w, acc.w);
        }
        sred[t] = acc;
        __syncthreads();
        if (fc == 0) {
            float4 a = sred[t], b = sred[t+64], c = sred[t+128], d = sred[t+192];
            float4 bi = ((const float4*)hyp_b2)[m4];
            float4 r;
            r.x = a.x + b.x + c.x + d.x + bi.x;
            r.y = a.y + b.y + c.y + d.y + bi.y;
            r.z = a.z + b.z + c.z + d.z + bi.z;
            r.w = a.w + b.w + c.w + d.w + bi.w;
            ((float4*)g_W)[m4] = r;
        }
    } else if (bid < 384) {
        int idx = (bid - 128)*256 + t;
        int k = idx >> 8, j = idx & 255;
        g_wrz[idx] = (k < 128) ? gwi[j*128 + k] : gwh[j*128 + (k - 128)];
    } else if (bid < 512) {
        int idx = (bid - 384)*256 + t;
        int k = idx >> 8, j = idx & 255;
        g_wn[idx] = (j < 128) ? gwi[(256 + j)*128 + k] : gwh[(128 + j)*128 + k];
    } else if (bid == 512) {
        if (t < H) {
            float a = merger_w[t], b = merger_w[H + t];
            float m = fmaxf(a, b);
            float e0 = expf(a - m), e1 = expf(b - m);
            float inv = 1.f / (e0 + e1);
            g_msm[t]     = e0 * inv;
            g_msm[H + t] = e1 * inv;
        }
    } else {
        __shared__ float c[QED];
        int r = bid - 513;
        float rqv = rq[r];
        if (t < QED) c[t] = cospif((float)t * rqv);
        if (t == 0) out[OFF_RQ + r] = rqv;
        __syncthreads();
        if (t < H) {
            float acc = phi_b[t];
            #pragma unroll 8
            for (int f = 0; f < QED; f++) acc = fmaf(c[f], phi_w[f*H + t], acc);
            g_qphi[r*H + t] = fmaxf(acc, 0.f);
        }
    }
}

// ---------------------------------------------------------------------------
// fused main: fc1 -> emb -> merge -> GRU -> fc2 -> sort.
// 128 threads, 16 rows/block, 256 blocks, 2 CTAs/SM.
// thread: rowA = lane&7 (rows rowA, rowA+8); c0 = (warp*4 + (lane>>3))*8.
#define ROWS 16
#define SC_STR 257
#define SX_STR 129
#define SC_F (ROWS*SC_STR)
#define SX_F (ROWS*SX_STR)
#define SB_F (3*4096)
#define SMEM_BYTES ((SC_F + SX_F + SB_F)*4)

__device__ __forceinline__ void stage16k(unsigned sbu, int bufi,
                                         const float* src, int tid) {
    unsigned d = sbu + (unsigned)(bufi*16384 + tid*16);
    const char* s = (const char*)src + tid*16;
    #pragma unroll
    for (int i = 0; i < 8; i++) cpa16(d + i*2048, s + i*2048);
}

__global__ __launch_bounds__(128, 2)
void k_main(const float* __restrict__ in, const float* __restrict__ hprev,
            const float* __restrict__ fc1_w, const float* __restrict__ fc1_b,
            const float* __restrict__ gbi,  const float* __restrict__ gbh,
            const float* __restrict__ fc2_w, const float* __restrict__ fc2_b,
            float* __restrict__ out) {
    extern __shared__ float smem[];
    float* sC = smem;
    float* sX = smem + SC_F;
    float* sB = smem + SC_F + SX_F;
    unsigned sbu = (unsigned)__cvta_generic_to_shared(sB);

    const int tid  = threadIdx.x;
    const int lane = tid & 31;
    const int warp = tid >> 5;              // 0..3
    const int rowA = lane & 7;
    const int c0   = (warp*4 + (lane >> 3))*8;   // 0..120
    const int row0 = blockIdx.x * ROWS;

    // stage input A [16][256] -> sC
    {
        const float4* src = (const float4*)(in + row0*E);
        #pragma unroll
        for (int i = tid; i < 1024; i += 128) {
            float4 v = src[i];
            int f = i * 4;
            int r = f >> 8, cc = f & 255;
            float* p = sC + r*SC_STR + cc;
            p[0] = v.x; p[1] = v.y; p[2] = v.z; p[3] = v.w;
        }
    }
    stage16k(sbu, 0, fc1_w, tid); cpcommit();

    // ======== FC1 : tiles g=0..7, KT=32, width 128 ========
    u64t X0[4], X1[4];
    {
        float4 b0 = *(const float4*)(fc1_b + c0);
        float4 b1 = *(const float4*)(fc1_b + c0 + 4);
        X0[0] = pk2b(b0.x, b0.y); X0[1] = pk2b(b0.z, b0.w);
        X0[2] = pk2b(b1.x, b1.y); X0[3] = pk2b(b1.z, b1.w);
        X1[0] = X0[0]; X1[1] = X0[1]; X1[2] = X0[2]; X1[3] = X0[3];
    }
    #pragma unroll 1
    for (int t = 0; t < 8; t++) {
        int g = t;
        const float* nsrc = (t < 7) ? (fc1_w + (t+1)*4096) : g_W;
        stage16k(sbu, (g+1)%3, nsrc, tid); cpcommit();
        cpwait1();
        __syncthreads();
        const float* bw  = sB + (g%3)*4096;
        const float* a0p = sC + rowA*SC_STR + t*32;
        const float* a1p = a0p + 8*SC_STR;
        #pragma unroll 8
        for (int kk = 0; kk < 32; kk++) {
            const float* wr = bw + kk*128 + c0;
            ulonglong2 w01 = *(const ulonglong2*)wr;
            ulonglong2 w23 = *(const ulonglong2*)(wr + 4);
            u64t a0 = pk2(a0p[kk]);
            u64t a1 = pk2(a1p[kk]);
            fma2(X0[0], a0, w01.x); fma2(X0[1], a0, w01.y);
            fma2(X0[2], a0, w23.x); fma2(X0[3], a0, w23.y);
            fma2(X1[0], a1, w01.x); fma2(X1[1], a1, w01.y);
            fma2(X1[2], a1, w23.x); fma2(X1[3], a1, w23.y);
        }
    }
    {
        float* xo0 = sX + rowA*SX_STR + c0;
        float* xo1 = xo0 + 8*SX_STR;
        #pragma unroll
        for (int cc = 0; cc < 4; cc++) {
            float2 v0 = upk(X0[cc]);
            float2 v1 = upk(X1[cc]);
            xo0[2*cc]   = fmaxf(v0.x, 0.f); xo0[2*cc+1] = fmaxf(v0.y, 0.f);
            xo1[2*cc]   = fmaxf(v1.x, 0.f); xo1[2*cc+1] = fmaxf(v1.y, 0.f);
        }
    }

    // ======== EMB : tiles g=8..15, KT=16, width 256 ========
    u64t P0[4] = {0,0,0,0}, P1[4] = {0,0,0,0};
    u64t Q0[4] = {0,0,0,0}, Q1[4] = {0,0,0,0};
    #pragma unroll 1
    for (int t = 0; t < 8; t++) {
        int g = 8 + t;
        const float* nsrc = (t < 7) ? (g_W + (t+1)*4096) : g_wrz;
        stage16k(sbu, (g+1)%3, nsrc, tid); cpcommit();
        cpwait1();
        __syncthreads();
        const float* bw  = sB + (g%3)*4096;
        const float* a0p = sX + rowA*SX_STR + t*16;
        const float* a1p = a0p + 8*SX_STR;
        #pragma unroll 4
        for (int kk = 0; kk < 16; kk++) {
            const float* wr0 = bw + kk*256 + c0;
            ulonglong2 p01 = *(const ulonglong2*)wr0;
            ulonglong2 p23 = *(const ulonglong2*)(wr0 + 4);
            ulonglong2 q01 = *(const ulonglong2*)(wr0 + 128);
            ulonglong2 q23 = *(const ulonglong2*)(wr0 + 132);
            u64t a0 = pk2(a0p[kk]);
            u64t a1 = pk2(a1p[kk]);
            fma2(P0[0], a0, p01.x); fma2(P0[1], a0, p01.y);
            fma2(P0[2], a0, p23.x); fma2(P0[3], a0, p23.y);
            fma2(P1[0], a1, p01.x); fma2(P1[1], a1, p01.y);
            fma2(P1[2], a1, p23.x); fma2(P1[3], a1, p23.y);
            fma2(Q0[0], a0, q01.x); fma2(Q0[1], a0, q01.y);
            fma2(Q0[2], a0, q23.x); fma2(Q0[3], a0, q23.y);
            fma2(Q1[0], a1, q01.x); fma2(Q1[1], a1, q01.y);
            fma2(Q1[2], a1, q23.x); fma2(Q1[3], a1, q23.y);
        }
    }

    // ---- merge + relu -> x2 into sC[0,128); stage hprev -> sC[128,256)
    {
        float4 m0a = *(const float4*)(g_msm + c0);
        float4 m0b = *(const float4*)(g_msm + c0 + 4);
        float4 m1a = *(const float4*)(g_msm + H + c0);
        float4 m1b = *(const float4*)(g_msm + H + c0 + 4);
        float m0v[8] = {m0a.x,m0a.y,m0a.z,m0a.w,m0b.x,m0b.y,m0b.z,m0b.w};
        float m1v[8] = {m1a.x,m1a.y,m1a.z,m1a.w,m1b.x,m1b.y,m1b.z,m1b.w};
        float* co0 = sC + rowA*SC_STR + c0;
        float* co1 = co0 + 8*SC_STR;
        #pragma unroll
        for (int cc = 0; cc < 4; cc++) {
            float2 a0 = upk(P0[cc]); float2 b0 = upk(Q0[cc]);
            float2 a1 = upk(P1[cc]); float2 b1 = upk(Q1[cc]);
            co0[2*cc]   = fmaxf(fmaf(m0v[2*cc],   a0.x, m1v[2*cc]  *b0.x), 0.f);
            co0[2*cc+1] = fmaxf(fmaf(m0v[2*cc+1], a0.y, m1v[2*cc+1]*b0.y), 0.f);
            co1[2*cc]   = fmaxf(fmaf(m0v[2*cc],   a1.x, m1v[2*cc]  *b1.x), 0.f);
            co1[2*cc+1] = fmaxf(fmaf(m0v[2*cc+1], a1.y, m1v[2*cc+1]*b1.y), 0.f);
        }
        const float4* hsrc = (const float4*)(hprev + row0*H);
        #pragma unroll
        for (int i = tid; i < 512; i += 128) {
            float4 v = hsrc[i];
            int f = i * 4;
            int r = f >> 7, cc = f & 127;
            float* p = sC + r*SC_STR + 128 + cc;
            p[0] = v.x; p[1] = v.y; p[2] = v.z; p[3] = v.w;
        }
    }

    // ======== GRU r,z : tiles g=16..31 ========
    float rs[2][8], zs[2][8];
    {
        u64t R0[4], R1[4], Z0[4], Z1[4];
        {
            float4 bi0 = *(const float4*)(gbi + c0);
            float4 bi1 = *(const float4*)(gbi + c0 + 4);
            float4 bh0 = *(const float4*)(gbh + c0);
            float4 bh1 = *(const float4*)(gbh + c0 + 4);
            R0[0] = pk2b(bi0.x+bh0.x, bi0.y+bh0.y);
            R0[1] = pk2b(bi0.z+bh0.z, bi0.w+bh0.w);
            R0[2] = pk2b(bi1.x+bh1.x, bi1.y+bh1.y);
            R0[3] = pk2b(bi1.z+bh1.z, bi1.w+bh1.w);
            float4 ci0 = *(const float4*)(gbi + H + c0);
            float4 ci1 = *(const float4*)(gbi + H + c0 + 4);
            float4 ch0 = *(const float4*)(gbh + H + c0);
            float4 ch1 = *(const float4*)(gbh + H + c0 + 4);
            Z0[0] = pk2b(ci0.x+ch0.x, ci0.y+ch0.y);
            Z0[1] = pk2b(ci0.z+ch0.z, ci0.w+ch0.w);
            Z0[2] = pk2b(ci1.x+ch1.x, ci1.y+ch1.y);
            Z0[3] = pk2b(ci1.z+ch1.z, ci1.w+ch1.w);
            #pragma unroll
            for (int i = 0; i < 4; i++) { R1[i] = R0[i]; Z1[i] = Z0[i]; }
        }
        #pragma unroll 1
        for (int t = 0; t < 16; t++) {
            int g = 16 + t;
            const float* nsrc = (t < 15) ? (g_wrz + (t+1)*4096) : g_wn;
            stage16k(sbu, (g+1)%3, nsrc, tid); cpcommit();
            cpwait1();
            __syncthreads();
            const float* bw  = sB + (g%3)*4096;
            const float* a0p = sC + rowA*SC_STR + t*16;
            const float* a1p = a0p + 8*SC_STR;
            #pragma unroll 4
            for (int kk = 0; kk < 16; kk++) {
                const float* wr0 = bw + kk*256 + c0;
                ulonglong2 p01 = *(const ulonglong2*)wr0;
                ulonglong2 p23 = *(const ulonglong2*)(wr0 + 4);
                ulonglong2 q01 = *(const ulonglong2*)(wr0 + 128);
                ulonglong2 q23 = *(const ulonglong2*)(wr0 + 132);
                u64t a0 = pk2(a0p[kk]);
                u64t a1 = pk2(a1p[kk]);
                fma2(R0[0], a0, p01.x); fma2(R0[1], a0, p01.y);
                fma2(R0[2], a0, p23.x); fma2(R0[3], a0, p23.y);
                fma2(R1[0], a1, p01.x); fma2(R1[1], a1, p01.y);
                fma2(R1[2], a1, p23.x); fma2(R1[3], a1, p23.y);
                fma2(Z0[0], a0, q01.x); fma2(Z0[1], a0, q01.y);
                fma2(Z0[2], a0, q23.x); fma2(Z0[3], a0, q23.y);
                fma2(Z1[0], a1, q01.x); fma2(Z1[1], a1, q01.y);
                fma2(Z1[2], a1, q23.x); fma2(Z1[3], a1, q23.y);
            }
        }
        #pragma unroll
        for (int cc = 0; cc < 4; cc++) {
            float2 r0 = upk(R0[cc]); float2 r1 = upk(R1[cc]);
            float2 z0 = upk(Z0[cc]); float2 z1 = upk(Z1[cc]);
            rs[0][2*cc] = sigm(r0.x); rs[0][2*cc+1] = sigm(r0.y);
            rs[1][2*cc] = sigm(r1.x); rs[1][2*cc+1] = sigm(r1.y);
            zs[0][2*cc] = sigm(z0.x); zs[0][2*cc+1] = sigm(z0.y);
            zs[1][2*cc] = sigm(z1.x); zs[1][2*cc+1] = sigm(z1.y);
        }
    }

    // ======== GRU n : tiles g=32..39 ========
    {
        u64t N0[4], N1[4], G0[4], G1[4];
        {
            float4 ni0 = *(const float4*)(gbi + 2*H + c0);
            float4 ni1 = *(const float4*)(gbi + 2*H + c0 + 4);
            float4 nh0 = *(const float4*)(gbh + 2*H + c0);
            float4 nh1 = *(const float4*)(gbh + 2*H + c0 + 4);
            N0[0] = pk2b(ni0.x, ni0.y); N0[1] = pk2b(ni0.z, ni0.w);
            N0[2] = pk2b(ni1.x, ni1.y); N0[3] = pk2b(ni1.z, ni1.w);
            G0[0] = pk2b(nh0.x, nh0.y); G0[1] = pk2b(nh0.z, nh0.w);
            G0[2] = pk2b(nh1.x, nh1.y); G0[3] = pk2b(nh1.z, nh1.w);
            #pragma unroll
            for (int i = 0; i < 4; i++) { N1[i] = N0[i]; G1[i] = G0[i]; }
        }
        #pragma unroll 1
        for (int t = 0; t < 8; t++) {
            int g = 32 + t;
            if (t < 7) { stage16k(sbu, (g+1)%3, g_wn + (t+1)*4096, tid); cpcommit(); cpwait1(); }
            else cpwait0();
            __syncthreads();
            const float* bw  = sB + (g%3)*4096;
            const float* a0p = sC + rowA*SC_STR + t*16;
            const float* a1p = a0p + 8*SC_STR;
            #pragma unroll 4
            for (int kk = 0; kk < 16; kk++) {
                const float* wr0 = bw + kk*256 + c0;
                ulonglong2 p01 = *(const ulonglong2*)wr0;
                ulonglong2 p23 = *(const ulonglong2*)(wr0 + 4);
                ulonglong2 q01 = *(const ulonglong2*)(wr0 + 128);
                ulonglong2 q23 = *(const ulonglong2*)(wr0 + 132);
                u64t x0 = pk2(a0p[kk]);
                u64t x1 = pk2(a1p[kk]);
                u64t h0 = pk2(a0p[kk + 128]);
                u64t h1 = pk2(a1p[kk + 128]);
                fma2(N0[0], x0, p01.x); fma2(N0[1], x0, p01.y);
                fma2(N0[2], x0, p23.x); fma2(N0[3], x0, p23.y);
                fma2(N1[0], x1, p01.x); fma2(N1[1], x1, p01.y);
                fma2(N1[2], x1, p23.x); fma2(N1[3], x1, p23.y);
                fma2(G0[0], h0, q01.x); fma2(G0[1], h0, q01.y);
                fma2(G0[2], h0, q23.x); fma2(G0[3], h0, q23.y);
                fma2(G1[0], h1, q01.x); fma2(G1[1], h1, q01.y);
                fma2(G1[2], h1, q23.x); fma2(G1[3], h1, q23.y);
            }
        }

        // finalize h (reads hp from sC before any sC rewrite)
        float hv0[8], hv1[8];
        const float* hp0 = sC + rowA*SC_STR + 128 + c0;
        const float* hp1 = hp0 + 8*SC_STR;
        #pragma unroll
        for (int cc = 0; cc < 4; cc++) {
            float2 nv0 = upk(N0[cc]); float2 gv0 = upk(G0[cc]);
            float2 nv1 = upk(N1[cc]); float2 gv1 = upk(G1[cc]);
            float n00 = tanhf(fmaf(rs[0][2*cc],   gv0.x, nv0.x));
            float n01 = tanhf(fmaf(rs[0][2*cc+1], gv0.y, nv0.y));
            float n10 = tanhf(fmaf(rs[1][2*cc],   gv1.x, nv1.x));
            float n11 = tanhf(fmaf(rs[1][2*cc+1], gv1.y, nv1.y));
            hv0[2*cc]   = (1.f - zs[0][2*cc])  * n00 + zs[0][2*cc]  * hp0[2*cc];
            hv0[2*cc+1] = (1.f - zs[0][2*cc+1])* n01 + zs[0][2*cc+1]* hp0[2*cc+1];
            hv1[2*cc]   = (1.f - zs[1][2*cc])  * n10 + zs[1][2*cc]  * hp1[2*cc];
            hv1[2*cc+1] = (1.f - zs[1][2*cc+1])* n11 + zs[1][2*cc+1]* hp1[2*cc+1];
        }
        int r0g = row0 + rowA, r1g = r0g + 8;
        *(float4*)&out[OFF_H + r0g*H + c0]     = make_float4(hv0[0], hv0[1], hv0[2], hv0[3]);
        *(float4*)&out[OFF_H + r0g*H + c0 + 4] = make_float4(hv0[4], hv0[5], hv0[6], hv0[7]);
        *(float4*)&out[OFF_H + r1g*H + c0]     = make_float4(hv1[0], hv1[1], hv1[2], hv1[3]);
        *(float4*)&out[OFF_H + r1g*H + c0 + 4] = make_float4(hv1[4], hv1[5], hv1[6], hv1[7]);

        __syncthreads();           // everyone done reading sC (x2/hp)

        // write h into sC cols [0,128)
        float* ho0 = sC + rowA*SC_STR + c0;
        float* ho1 = ho0 + 8*SC_STR;
        #pragma unroll
        for (int cc = 0; cc < 8; cc++) { ho0[cc] = hv0[cc]; ho1[cc] = hv1[cc]; }
    }

    // ======== epilogue: fc2 + transpose + sort ========
    // sB[0..2064): qphi tile [16][129] ; sB+4224: ssq [16][112]
    // sX[0..2048): fc2_w padded [128][16]
    {
        float* sQ = sB;
        float* sW = sX;
        float* ssq = sB + 4224;
        #pragma unroll
        for (int i = tid; i < 2048; i += 128) {
            int qq = i >> 7, j = i & 127;
            sQ[qq*129 + j] = g_qphi[(row0 + qq)*H + j];
        }
        for (int i = tid; i < H*NA; i += 128) {
            int j = i / NA, na = i - j*NA;
            sW[j*16 + na] = fc2_w[i];
        }
        __syncthreads();

        {   // 128 threads: row 0..15 x qi 0..7
            const int row = tid & 15;
            const int qi  = tid >> 4;
            const float* hrow = sC + row*SC_STR;
            const float* qrow = sQ + ((row >> 3)*8 + qi)*129;
            u64t acc[7];
            #pragma unroll
            for (int p = 0; p < 7; p++) acc[p] = pk2b(fc2_b[2*p], fc2_b[2*p+1]);
            #pragma unroll 4
            for (int j = 0; j < H; j++) {
                float hq = hrow[j] * qrow[j];
                u64t h2 = pk2(hq);
                const ulonglong2* wp = (const ulonglong2*)(sW + j*16);
                ulonglong2 w0 = wp[0], w1 = wp[1];
                u64t w2 = *(const u64t*)(sW + j*16 + 8);
                u64t w3 = *(const u64t*)(sW + j*16 + 10);
                u64t w4 = *(const u64t*)(sW + j*16 + 12);
                fma2(acc[0], h2, w0.x); fma2(acc[1], h2, w0.y);
                fma2(acc[2], h2, w1.x); fma2(acc[3], h2, w1.y);
                fma2(acc[4], h2, w2);   fma2(acc[5], h2, w3);
                fma2(acc[6], h2, w4);
            }
            #pragma unroll
            for (int p = 0; p < 7; p++) {
                float2 v = upk(acc[p]);
                ssq[row*112 + (2*p)*8   + qi] = v.x;
                ssq[row*112 + (2*p+1)*8 + qi] = v.y;
            }
        }
        __syncthreads();

        // sort: 224 (row,na) pairs
        for (int p = tid; p < ROWS*NA; p += 128) {
            int r = p / NA, na = p - r*NA;
            const float* s = ssq + r*112 + na*8;
            float v[NQ];
            #pragma unroll
            for (int k = 0; k < NQ; k++) v[k] = s[k];
            #pragma unroll
            for (int i = 1; i < NQ; i++) {
                float key = v[i];
                int q = i - 1;
                while (q >= 0 && v[q] > key) { v[q+1] = v[q]; q--; }
                v[q+1] = key;
            }
            float* o = out + OFF_SQ + (row0 + r)*112 + na*8;
            *(float4*)o       = make_float4(v[0], v[1], v[2], v[3]);
            *(float4*)(o + 4) = make_float4(v[4], v[5], v[6], v[7]);
        }
    }
}

// ---------------------------------------------------------------------------
extern "C" void kernel_launch(void* const* d_in, const int* in_sizes, int n_in,
                              void* d_out, int out_size) {
    const float* in        = (const float*)d_in[0];
    const float* hidden    = (const float*)d_in[1];
    const float* rqs       = (const float*)d_in[2];
    const float* fc1_w     = (const float*)d_in[3];
    const float* fc1_b     = (const float*)d_in[4];
    const float* hyp_w1    = (const float*)d_in[5];
    const float* hyp_b1    = (const float*)d_in[6];
    const float* hyp_w2    = (const float*)d_in[7];
    const float* hyp_b2    = (const float*)d_in[8];
    const float* merger_w  = (const float*)d_in[9];
    const float* gru_wi    = (const float*)d_in[10];
    const float* gru_wh    = (const float*)d_in[11];
    const float* gru_bi    = (const float*)d_in[12];
    const float* gru_bh    = (const float*)d_in[13];
    const float* phi_w     = (const float*)d_in[14];
    const float* phi_b     = (const float*)d_in[15];
    const float* fc2_w     = (const float*)d_in[16];
    const float* fc2_b     = (const float*)d_in[17];
    float* out = (float*)d_out;

    static int smem_set = 0;
    if (!smem_set) {
        cudaFuncSetAttribute(k_main, cudaFuncAttributeMaxDynamicSharedMemorySize,
                             SMEM_BYTES);
        smem_set = 1;
    }

    k_wprep<<<513 + BSG*NQ, 256>>>(hyp_w1, hyp_b1, hyp_w2, hyp_b2, merger_w,
                                   gru_wi, gru_wh, rqs, phi_w, phi_b, out);
    k_main<<<BS/ROWS, 128, SMEM_BYTES>>>(in, hidden, fc1_w, fc1_b, gru_bi, gru_bh,
                                         fc2_w, fc2_b, out);
}

// round 10
// speedup vs baseline: 1.3201x; 1.0423x over previous
#include <cuda_runtime.h>
#include <math.h>

// dims
#define E    256
#define H    128
#define NQ   8
#define QED  64
#define HYP  64
#define NA   14
#define BS   4096
#define BSG  512
#define WSZ  32768

// output layout: sorted_q [BS,NA,NQ] | h [BS,H] | rq [BSG,NQ]
#define OFF_SQ 0
#define OFF_H  (BS*NA*NQ)
#define OFF_RQ (OFF_H + BS*H)

// scratch
__device__ __align__(16) float g_msm[2*H];
__device__ __align__(16) float g_W[H*2*H];        // [128][256]
__device__ __align__(16) float g_wrz[2*H*2*H];    // [256][256]
__device__ __align__(16) float g_wn[H*2*H];       // [128][256]

typedef unsigned long long u64t;
__device__ __forceinline__ u64t pk2(float a) {
    u64t r; asm("mov.b64 %0, {%1,%1};" : "=l"(r) : "f"(a)); return r;
}
__device__ __forceinline__ u64t pk2b(float a, float b) {
    u64t r; asm("mov.b64 %0, {%1,%2};" : "=l"(r) : "f"(a), "f"(b)); return r;
}
__device__ __forceinline__ void fma2(u64t& d, u64t a, u64t b) {
    asm("fma.rn.f32x2 %0, %1, %2, %3;" : "=l"(d) : "l"(a), "l"(b), "l"(d));
}
__device__ __forceinline__ float2 upk(u64t v) {
    float2 f; asm("mov.b64 {%0,%1}, %2;" : "=f"(f.x), "=f"(f.y) : "l"(v)); return f;
}
__device__ __forceinline__ float sigm(float x) {
    return __fdividef(1.f, 1.f + __expf(-x));
}

// cp.async helpers
__device__ __forceinline__ void cpa16(unsigned s, const void* g) {
    asm volatile("cp.async.cg.shared.global [%0], [%1], 16;" :: "r"(s), "l"(g));
}
__device__ __forceinline__ void cpcommit() { asm volatile("cp.async.commit_group;"); }
__device__ __forceinline__ void cpwait0()  { asm volatile("cp.async.wait_group 0;"); }

// ---------------------------------------------------------------------------
// weight-prep: buildW + GRU transposes + msm. 256 threads/block, 513 blocks.
__global__ __launch_bounds__(256)
void k_wprep(const float* __restrict__ hyp_w1,
             const float* __restrict__ hyp_b1,
             const float* __restrict__ hyp_w2,
             const float* __restrict__ hyp_b2,
             const float* __restrict__ merger_w,
             const float* __restrict__ gwi,
             const float* __restrict__ gwh) {
    int bid = blockIdx.x, t = threadIdx.x;
    if (bid < 128) {
        __shared__ float sh[HYP];
        __shared__ float4 sred[256];
        if (t < HYP) {
            float s = hyp_b1[t];
            #pragma unroll
            for (int q = 0; q < NQ; q++) s += hyp_w1[q*HYP + t];
            sh[t] = fmaxf(s, 0.f);
        }
        __syncthreads();
        int m4loc = t & 63, fc = t >> 6;
        int m4 = bid*64 + m4loc;
        const float4* src = (const float4*)hyp_w2;
        float4 acc = make_float4(0.f, 0.f, 0.f, 0.f);
        #pragma unroll
        for (int f = 0; f < 16; f++) {
            float s = sh[fc*16 + f];
            float4 v = src[(fc*16 + f)*8192 + m4];
            acc.x = fmaf(s, v.x, acc.x);
            acc.y = fmaf(s, v.y, acc.y);
            acc.z = fmaf(s, v.z, acc.z);
            acc.w = fmaf(s, v.w, acc.w);
        }
        sred[t] = acc;
        __syncthreads();
        if (fc == 0) {
            float4 a = sred[t], b = sred[t+64], c = sred[t+128], d = sred[t+192];
            float4 bi = ((const float4*)hyp_b2)[m4];
            float4 r;
            r.x = a.x + b.x + c.x + d.x + bi.x;
            r.y = a.y + b.y + c.y + d.y + bi.y;
            r.z = a.z + b.z + c.z + d.z + bi.z;
            r.w = a.w + b.w + c.w + d.w + bi.w;
            ((float4*)g_W)[m4] = r;
        }
    } else if (bid < 384) {
        int idx = (bid - 128)*256 + t;
        int k = idx >> 8, j = idx & 255;
        g_wrz[idx] = (k < 128) ? gwi[j*128 + k] : gwh[j*128 + (k - 128)];
    } else if (bid < 512) {
        int idx = (bid - 384)*256 + t;
        int k = idx >> 8, j = idx & 255;
        g_wn[idx] = (j < 128) ? gwi[(256 + j)*128 + k] : gwh[(128 + j)*128 + k];
    } else {
        if (t < H) {
            float a = merger_w[t], b = merger_w[H + t];
            float m = fmaxf(a, b);
            float e0 = expf(a - m), e1 = expf(b - m);
            float inv = 1.f / (e0 + e1);
            g_msm[t]     = e0 * inv;
            g_msm[H + t] = e1 * inv;
        }
    }
}

// ---------------------------------------------------------------------------
// fused main: fc1 -> emb -> merge -> GRU -> qphi -> fc2 -> sort.
// 128 threads, 16 rows/block, 256 blocks, 2 CTAs/SM.
// rowA = lane&7 (rows rowA, rowA+8); c0 = (warp*4 + (lane>>3))*8.
// 20 weight tiles of 32KB, 2 buffers, 1 barrier per tile.
#define ROWS 16
#define SC_STR 257
#define SX_STR 129
#define SC_F (ROWS*SC_STR)
#define SX_F (ROWS*SX_STR)
#define SB_F (2*8192)
#define SMEM_BYTES ((SC_F + SX_F + SB_F)*4)

// 32KB tile stage: 8192 floats, 128 threads x 16 chunks of 16B
__device__ __forceinline__ void stage32k(unsigned sbu, int bufi,
                                         const float* src, int tid) {
    unsigned d = sbu + (unsigned)(bufi*32768 + tid*16);
    const char* s = (const char*)src + tid*16;
    #pragma unroll
    for (int i = 0; i < 16; i++) cpa16(d + i*2048, s + i*2048);
}

__global__ __launch_bounds__(128, 2)
void k_main(const float* __restrict__ in, const float* __restrict__ hprev,
            const float* __restrict__ fc1_w, const float* __restrict__ fc1_b,
            const float* __restrict__ gbi,  const float* __restrict__ gbh,
            const float* __restrict__ rq_in,
            const float* __restrict__ phi_w, const float* __restrict__ phi_b,
            const float* __restrict__ fc2_w, const float* __restrict__ fc2_b,
            float* __restrict__ out) {
    extern __shared__ float smem[];
    float* sC = smem;
    float* sX = smem + SC_F;
    float* sB = smem + SC_F + SX_F;
    unsigned sbu = (unsigned)__cvta_generic_to_shared(sB);

    const int tid  = threadIdx.x;
    const int lane = tid & 31;
    const int warp = tid >> 5;              // 0..3
    const int rowA = lane & 7;
    const int c0   = (warp*4 + (lane >> 3))*8;   // 0..120
    const int row0 = blockIdx.x * ROWS;

    stage32k(sbu, 0, fc1_w, tid); cpcommit();

    // stage input A [16][256] -> sC
    {
        const float4* src = (const float4*)(in + row0*E);
        #pragma unroll
        for (int i = tid; i < 1024; i += 128) {
            float4 v = src[i];
            int f = i * 4;
            int r = f >> 8, cc = f & 255;
            float* p = sC + r*SC_STR + cc;
            p[0] = v.x; p[1] = v.y; p[2] = v.z; p[3] = v.w;
        }
    }

    // ======== FC1 : tiles g=0..3, KT=64, width 128 ========
    u64t X0[4], X1[4];
    {
        float4 b0 = *(const float4*)(fc1_b + c0);
        float4 b1 = *(const float4*)(fc1_b + c0 + 4);
        X0[0] = pk2b(b0.x, b0.y); X0[1] = pk2b(b0.z, b0.w);
        X0[2] = pk2b(b1.x, b1.y); X0[3] = pk2b(b1.z, b1.w);
        X1[0] = X0[0]; X1[1] = X0[1]; X1[2] = X0[2]; X1[3] = X0[3];
    }
    #pragma unroll 1
    for (int t = 0; t < 4; t++) {
        int g = t;
        cpwait0();
        __syncthreads();
        const float* nsrc = (t < 3) ? (fc1_w + (t+1)*8192) : g_W;
        stage32k(sbu, (g+1)&1, nsrc, tid); cpcommit();
        const float* bw  = sB + (g&1)*8192;
        const float* a0p = sC + rowA*SC_STR + t*64;
        const float* a1p = a0p + 8*SC_STR;
        #pragma unroll 8
        for (int kk = 0; kk < 64; kk++) {
            const float* wr = bw + kk*128 + c0;
            ulonglong2 w01 = *(const ulonglong2*)wr;
            ulonglong2 w23 = *(const ulonglong2*)(wr + 4);
            u64t a0 = pk2(a0p[kk]);
            u64t a1 = pk2(a1p[kk]);
            fma2(X0[0], a0, w01.x); fma2(X0[1], a0, w01.y);
            fma2(X0[2], a0, w23.x); fma2(X0[3], a0, w23.y);
            fma2(X1[0], a1, w01.x); fma2(X1[1], a1, w01.y);
            fma2(X1[2], a1, w23.x); fma2(X1[3], a1, w23.y);
        }
    }
    {
        float* xo0 = sX + rowA*SX_STR + c0;
        float* xo1 = xo0 + 8*SX_STR;
        #pragma unroll
        for (int cc = 0; cc < 4; cc++) {
            float2 v0 = upk(X0[cc]);
            float2 v1 = upk(X1[cc]);
            xo0[2*cc]   = fmaxf(v0.x, 0.f); xo0[2*cc+1] = fmaxf(v0.y, 0.f);
            xo1[2*cc]   = fmaxf(v1.x, 0.f); xo1[2*cc+1] = fmaxf(v1.y, 0.f);
        }
    }

    // ======== EMB : tiles g=4..7, KT=32, width 256 ========
    u64t P0[4] = {0,0,0,0}, P1[4] = {0,0,0,0};
    u64t Q0[4] = {0,0,0,0}, Q1[4] = {0,0,0,0};
    #pragma unroll 1
    for (int t = 0; t < 4; t++) {
        int g = 4 + t;
        cpwait0();
        __syncthreads();
        const float* nsrc = (t < 3) ? (g_W + (t+1)*8192) : g_wrz;
        stage32k(sbu, (g+1)&1, nsrc, tid); cpcommit();
        const float* bw  = sB + (g&1)*8192;
        const float* a0p = sX + rowA*SX_STR + t*32;
        const float* a1p = a0p + 8*SX_STR;
        #pragma unroll 8
        for (int kk = 0; kk < 32; kk++) {
            const float* wr0 = bw + kk*256 + c0;
            ulonglong2 p01 = *(const ulonglong2*)wr0;
            ulonglong2 p23 = *(const ulonglong2*)(wr0 + 4);
            ulonglong2 q01 = *(const ulonglong2*)(wr0 + 128);
            ulonglong2 q23 = *(const ulonglong2*)(wr0 + 132);
            u64t a0 = pk2(a0p[kk]);
            u64t a1 = pk2(a1p[kk]);
            fma2(P0[0], a0, p01.x); fma2(P0[1], a0, p01.y);
            fma2(P0[2], a0, p23.x); fma2(P0[3], a0, p23.y);
            fma2(P1[0], a1, p01.x); fma2(P1[1], a1, p01.y);
            fma2(P1[2], a1, p23.x); fma2(P1[3], a1, p23.y);
            fma2(Q0[0], a0, q01.x); fma2(Q0[1], a0, q01.y);
            fma2(Q0[2], a0, q23.x); fma2(Q0[3], a0, q23.y);
            fma2(Q1[0], a1, q01.x); fma2(Q1[1], a1, q01.y);
            fma2(Q1[2], a1, q23.x); fma2(Q1[3], a1, q23.y);
        }
    }

    // ---- merge + relu -> x2 into sC[0,128); stage hprev -> sC[128,256)
    {
        float4 m0a = *(const float4*)(g_msm + c0);
        float4 m0b = *(const float4*)(g_msm + c0 + 4);
        float4 m1a = *(const float4*)(g_msm + H + c0);
        float4 m1b = *(const float4*)(g_msm + H + c0 + 4);
        float m0v[8] = {m0a.x,m0a.y,m0a.z,m0a.w,m0b.x,m0b.y,m0b.z,m0b.w};
        float m1v[8] = {m1a.x,m1a.y,m1a.z,m1a.w,m1b.x,m1b.y,m1b.z,m1b.w};
        float* co0 = sC + rowA*SC_STR + c0;
        float* co1 = co0 + 8*SC_STR;
        #pragma unroll
        for (int cc = 0; cc < 4; cc++) {
            float2 a0 = upk(P0[cc]); float2 b0 = upk(Q0[cc]);
            float2 a1 = upk(P1[cc]); float2 b1 = upk(Q1[cc]);
            co0[2*cc]   = fmaxf(fmaf(m0v[2*cc],   a0.x, m1v[2*cc]  *b0.x), 0.f);
            co0[2*cc+1] = fmaxf(fmaf(m0v[2*cc+1], a0.y, m1v[2*cc+1]*b0.y), 0.f);
            co1[2*cc]   = fmaxf(fmaf(m0v[2*cc],   a1.x, m1v[2*cc]  *b1.x), 0.f);
            co1[2*cc+1] = fmaxf(fmaf(m0v[2*cc+1], a1.y, m1v[2*cc+1]*b1.y), 0.f);
        }
        const float4* hsrc = (const float4*)(hprev + row0*H);
        #pragma unroll
        for (int i = tid; i < 512; i += 128) {
            float4 v = hsrc[i];
            int f = i * 4;
            int r = f >> 7, cc = f & 127;
            float* p = sC + r*SC_STR + 128 + cc;
            p[0] = v.x; p[1] = v.y; p[2] = v.z; p[3] = v.w;
        }
    }

    // ======== GRU r,z : tiles g=8..15, KT=32 ========
    float rs[2][8], zs[2][8];
    {
        u64t R0[4], R1[4], Z0[4], Z1[4];
        {
            float4 bi0 = *(const float4*)(gbi + c0);
            float4 bi1 = *(const float4*)(gbi + c0 + 4);
            float4 bh0 = *(const float4*)(gbh + c0);
            float4 bh1 = *(const float4*)(gbh + c0 + 4);
            R0[0] = pk2b(bi0.x+bh0.x, bi0.y+bh0.y);
            R0[1] = pk2b(bi0.z+bh0.z, bi0.w+bh0.w);
            R0[2] = pk2b(bi1.x+bh1.x, bi1.y+bh1.y);
            R0[3] = pk2b(bi1.z+bh1.z, bi1.w+bh1.w);
            float4 ci0 = *(const float4*)(gbi + H + c0);
            float4 ci1 = *(const float4*)(gbi + H + c0 + 4);
            float4 ch0 = *(const float4*)(gbh + H + c0);
            float4 ch1 = *(const float4*)(gbh + H + c0 + 4);
            Z0[0] = pk2b(ci0.x+ch0.x, ci0.y+ch0.y);
            Z0[1] = pk2b(ci0.z+ch0.z, ci0.w+ch0.w);
            Z0[2] = pk2b(ci1.x+ch1.x, ci1.y+ch1.y);
            Z0[3] = pk2b(ci1.z+ch1.z, ci1.w+ch1.w);
            #pragma unroll
            for (int i = 0; i < 4; i++) { R1[i] = R0[i]; Z1[i] = Z0[i]; }
        }
        #pragma unroll 1
        for (int t = 0; t < 8; t++) {
            int g = 8 + t;
            cpwait0();
            __syncthreads();
            const float* nsrc = (t < 7) ? (g_wrz + (t+1)*8192) : g_wn;
            stage32k(sbu, (g+1)&1, nsrc, tid); cpcommit();
            const float* bw  = sB + (g&1)*8192;
            const float* a0p = sC + rowA*SC_STR + t*32;
            const float* a1p = a0p + 8*SC_STR;
            #pragma unroll 8
            for (int kk = 0; kk < 32; kk++) {
                const float* wr0 = bw + kk*256 + c0;
                ulonglong2 p01 = *(const ulonglong2*)wr0;
                ulonglong2 p23 = *(const ulonglong2*)(wr0 + 4);
                ulonglong2 q01 = *(const ulonglong2*)(wr0 + 128);
                ulonglong2 q23 = *(const ulonglong2*)(wr0 + 132);
                u64t a0 = pk2(a0p[kk]);
                u64t a1 = pk2(a1p[kk]);
                fma2(R0[0], a0, p01.x); fma2(R0[1], a0, p01.y);
                fma2(R0[2], a0, p23.x); fma2(R0[3], a0, p23.y);
                fma2(R1[0], a1, p01.x); fma2(R1[1], a1, p01.y);
                fma2(R1[2], a1, p23.x); fma2(R1[3], a1, p23.y);
                fma2(Z0[0], a0, q01.x); fma2(Z0[1], a0, q01.y);
                fma2(Z0[2], a0, q23.x); fma2(Z0[3], a0, q23.y);
                fma2(Z1[0], a1, q01.x); fma2(Z1[1], a1, q01.y);
                fma2(Z1[2], a1, q23.x); fma2(Z1[3], a1, q23.y);
            }
        }
        #pragma unroll
        for (int cc = 0; cc < 4; cc++) {
            float2 r0 = upk(R0[cc]); float2 r1 = upk(R1[cc]);
            float2 z0 = upk(Z0[cc]); float2 z1 = upk(Z1[cc]);
            rs[0][2*cc] = sigm(r0.x); rs[0][2*cc+1] = sigm(r0.y);
            rs[1][2*cc] = sigm(r1.x); rs[1][2*cc+1] = sigm(r1.y);
            zs[0][2*cc] = sigm(z0.x); zs[0][2*cc+1] = sigm(z0.y);
            zs[1][2*cc] = sigm(z1.x); zs[1][2*cc+1] = sigm(z1.y);
        }
    }

    // ======== GRU n : tiles g=16..19, KT=32 ========
    {
        u64t N0[4], N1[4], G0[4], G1[4];
        {
            float4 ni0 = *(const float4*)(gbi + 2*H + c0);
            float4 ni1 = *(const float4*)(gbi + 2*H + c0 + 4);
            float4 nh0 = *(const float4*)(gbh + 2*H + c0);
            float4 nh1 = *(const float4*)(gbh + 2*H + c0 + 4);
            N0[0] = pk2b(ni0.x, ni0.y); N0[1] = pk2b(ni0.z, ni0.w);
            N0[2] = pk2b(ni1.x, ni1.y); N0[3] = pk2b(ni1.z, ni1.w);
            G0[0] = pk2b(nh0.x, nh0.y); G0[1] = pk2b(nh0.z, nh0.w);
            G0[2] = pk2b(nh1.x, nh1.y); G0[3] = pk2b(nh1.z, nh1.w);
            #pragma unroll
            for (int i = 0; i < 4; i++) { N1[i] = N0[i]; G1[i] = G0[i]; }
        }
        #pragma unroll 1
        for (int t = 0; t < 4; t++) {
            int g = 16 + t;
            cpwait0();
            __syncthreads();
            if (t < 3) { stage32k(sbu, (g+1)&1, g_wn + (t+1)*8192, tid); cpcommit(); }
            const float* bw  = sB + (g&1)*8192;
            const float* a0p = sC + rowA*SC_STR + t*32;
            const float* a1p = a0p + 8*SC_STR;
            #pragma unroll 8
            for (int kk = 0; kk < 32; kk++) {
                const float* wr0 = bw + kk*256 + c0;
                ulonglong2 p01 = *(const ulonglong2*)wr0;
                ulonglong2 p23 = *(const ulonglong2*)(wr0 + 4);
                ulonglong2 q01 = *(const ulonglong2*)(wr0 + 128);
                ulonglong2 q23 = *(const ulonglong2*)(wr0 + 132);
                u64t x0 = pk2(a0p[kk]);
                u64t x1 = pk2(a1p[kk]);
                u64t h0 = pk2(a0p[kk + 128]);
                u64t h1 = pk2(a1p[kk + 128]);
                fma2(N0[0], x0, p01.x); fma2(N0[1], x0, p01.y);
                fma2(N0[2], x0, p23.x); fma2(N0[3], x0, p23.y);
                fma2(N1[0], x1, p01.x); fma2(N1[1], x1, p01.y);
                fma2(N1[2], x1, p23.x); fma2(N1[3], x1, p23.y);
                fma2(G0[0], h0, q01.x); fma2(G0[1], h0, q01.y);
                fma2(G0[2], h0, q23.x); fma2(G0[3], h0, q23.y);
                fma2(G1[0], h1, q01.x); fma2(G1[1], h1, q01.y);
                fma2(G1[2], h1, q23.x); fma2(G1[3], h1, q23.y);
            }
        }

        // finalize h
        float hv0[8], hv1[8];
        const float* hp0 = sC + rowA*SC_STR + 128 + c0;
        const float* hp1 = hp0 + 8*SC_STR;
        #pragma unroll
        for (int cc = 0; cc < 4; cc++) {
            float2 nv0 = upk(N0[cc]); float2 gv0 = upk(G0[cc]);
            float2 nv1 = upk(N1[cc]); float2 gv1 = upk(G1[cc]);
            float n00 = tanhf(fmaf(rs[0][2*cc],   gv0.x, nv0.x));
            float n01 = tanhf(fmaf(rs[0][2*cc+1], gv0.y, nv0.y));
            float n10 = tanhf(fmaf(rs[1][2*cc],   gv1.x, nv1.x));
            float n11 = tanhf(fmaf(rs[1][2*cc+1], gv1.y, nv1.y));
            hv0[2*cc]   = (1.f - zs[0][2*cc])  * n00 + zs[0][2*cc]  * hp0[2*cc];
            hv0[2*cc+1] = (1.f - zs[0][2*cc+1])* n01 + zs[0][2*cc+1]* hp0[2*cc+1];
            hv1[2*cc]   = (1.f - zs[1][2*cc])  * n10 + zs[1][2*cc]  * hp1[2*cc];
            hv1[2*cc+1] = (1.f - zs[1][2*cc+1])* n11 + zs[1][2*cc+1]* hp1[2*cc+1];
        }
        int r0g = row0 + rowA, r1g = r0g + 8;
        *(float4*)&out[OFF_H + r0g*H + c0]     = make_float4(hv0[0], hv0[1], hv0[2], hv0[3]);
        *(float4*)&out[OFF_H + r0g*H + c0 + 4] = make_float4(hv0[4], hv0[5], hv0[6], hv0[7]);
        *(float4*)&out[OFF_H + r1g*H + c0]     = make_float4(hv1[0], hv1[1], hv1[2], hv1[3]);
        *(float4*)&out[OFF_H + r1g*H + c0 + 4] = make_float4(hv1[4], hv1[5], hv1[6], hv1[7]);

        __syncthreads();           // everyone done reading sC (x2/hp)

        // write h into sC cols [0,128)
        float* ho0 = sC + rowA*SC_STR + c0;
        float* ho1 = ho0 + 8*SC_STR;
        #pragma unroll
        for (int cc = 0; cc < 8; cc++) { ho0[cc] = hv0[cc]; ho1[cc] = hv1[cc]; }
    }

    // ======== epilogue: qphi + fc2 + transpose + sort ========
    // sB: sQ [16][129] at 0 ; ssq [16][112] at 2176 ;
    //     sPhi [64][160 swz] at 4096 ; sCos [16][68] at 14336
    // sX: sW fc2_w padded [128][16]
    {
        float* sQ   = sB;
        float* ssq  = sB + 2176;
        float* sPhi = sB + 4096;      // stride 160, j' = j + 4*(j>>4)
        float* sCos = sB + 14336;     // stride 68
        float* sW   = sX;

        // cos table + rq out: thread (qq = tid>>3, fb = tid&7)
        {
            int qq = tid >> 3, fb = tid & 7;
            float rqv = rq_in[row0 + qq];
            if (fb == 0) out[OFF_RQ + row0 + qq] = rqv;
            #pragma unroll
            for (int u = 0; u < 8; u++) {
                int f = fb*8 + u;
                sCos[qq*68 + f] = cospif((float)f * rqv);
            }
        }
        // stage phi_w swizzled + fc2_w padded
        #pragma unroll
        for (int i = tid; i < 2048; i += 128) {
            float4 v = ((const float4*)phi_w)[i];
            int f = i >> 5, jt = (i & 31)*4;
            float* p = sPhi + f*160 + jt + ((jt >> 4) << 2);
            p[0] = v.x; p[1] = v.y; p[2] = v.z; p[3] = v.w;
        }
        for (int i = tid; i < H*NA; i += 128) {
            int j = i / NA, na = i - j*NA;
            sW[j*16 + na] = fc2_w[i];
        }
        __syncthreads();

        // qphi: thread (qq = tid>>3, j0 = (tid&7)*16) -> 16 outputs
        {
            int qq = tid >> 3, fb = tid & 7;
            int j0 = fb * 16;
            const float* ph = sPhi + j0 + 4*fb;    // swizzled column base
            u64t acc[8];
            #pragma unroll
            for (int p = 0; p < 8; p++)
                acc[p] = pk2b(phi_b[j0 + 2*p], phi_b[j0 + 2*p + 1]);
            const float* crow = sCos + qq*68;
            #pragma unroll 8
            for (int f = 0; f < QED; f++) {
                u64t c2 = pk2(crow[f]);
                const float* pr = ph + f*160;
                ulonglong2 w01 = *(const ulonglong2*)pr;
                ulonglong2 w23 = *(const ulonglong2*)(pr + 4);
                ulonglong2 w45 = *(const ulonglong2*)(pr + 8);
                ulonglong2 w67 = *(const ulonglong2*)(pr + 12);
                fma2(acc[0], c2, w01.x); fma2(acc[1], c2, w01.y);
                fma2(acc[2], c2, w23.x); fma2(acc[3], c2, w23.y);
                fma2(acc[4], c2, w45.x); fma2(acc[5], c2, w45.y);
                fma2(acc[6], c2, w67.x); fma2(acc[7], c2, w67.y);
            }
            float* qo = sQ + qq*129 + j0;
            #pragma unroll
            for (int p = 0; p < 8; p++) {
                float2 v = upk(acc[p]);
                qo[2*p]   = fmaxf(v.x, 0.f);
                qo[2*p+1] = fmaxf(v.y, 0.f);
            }
        }
        __syncthreads();

        // fc2: thread (row = tid&15, qi = tid>>4)
        {
            const int row = tid & 15;
            const int qi  = tid >> 4;
            const float* hrow = sC + row*SC_STR;
            const float* qrow = sQ + ((row >> 3)*8 + qi)*129;
            u64t acc[7];
            #pragma unroll
            for (int p = 0; p < 7; p++) acc[p] = pk2b(fc2_b[2*p], fc2_b[2*p+1]);
            #pragma unroll 4
            for (int j = 0; j < H; j++) {
                float hq = hrow[j] * qrow[j];
                u64t h2 = pk2(hq);
                const ulonglong2* wp = (const ulonglong2*)(sW + j*16);
                ulonglong2 w0 = wp[0], w1 = wp[1];
                u64t w2 = *(const u64t*)(sW + j*16 + 8);
                u64t w3 = *(const u64t*)(sW + j*16 + 10);
                u64t w4 = *(const u64t*)(sW + j*16 + 12);
                fma2(acc[0], h2, w0.x); fma2(acc[1], h2, w0.y);
                fma2(acc[2], h2, w1.x); fma2(acc[3], h2, w1.y);
                fma2(acc[4], h2, w2);   fma2(acc[5], h2, w3);
                fma2(acc[6], h2, w4);
            }
            #pragma unroll
            for (int p = 0; p < 7; p++) {
                float2 v = upk(acc[p]);
                ssq[row*112 + (2*p)*8   + qi] = v.x;
                ssq[row*112 + (2*p+1)*8 + qi] = v.y;
            }
        }
        __syncthreads();

        // sort: 224 (row,na) pairs
        for (int p = tid; p < ROWS*NA; p += 128) {
            int r = p / NA, na = p - r*NA;
            const float* s = ssq + r*112 + na*8;
            float v[NQ];
            #pragma unroll
            for (int k = 0; k < NQ; k++) v[k] = s[k];
            #pragma unroll
            for (int i = 1; i < NQ; i++) {
                float key = v[i];
                int q = i - 1;
                while (q >= 0 && v[q] > key) { v[q+1] = v[q]; q--; }
                v[q+1] = key;
            }
            float* o = out + OFF_SQ + (row0 + r)*112 + na*8;
            *(float4*)o       = make_float4(v[0], v[1], v[2], v[3]);
            *(float4*)(o + 4) = make_float4(v[4], v[5], v[6], v[7]);
        }
    }
}

// ---------------------------------------------------------------------------
extern "C" void kernel_launch(void* const* d_in, const int* in_sizes, int n_in,
                              void* d_out, int out_size) {
    const float* in        = (const float*)d_in[0];
    const float* hidden    = (const float*)d_in[1];
    const float* rqs       = (const float*)d_in[2];
    const float* fc1_w     = (const float*)d_in[3];
    const float* fc1_b     = (const float*)d_in[4];
    const float* hyp_w1    = (const float*)d_in[5];
    const float* hyp_b1    = (const float*)d_in[6];
    const float* hyp_w2    = (const float*)d_in[7];
    const float* hyp_b2    = (const float*)d_in[8];
    const float* merger_w  = (const float*)d_in[9];
    const float* gru_wi    = (const float*)d_in[10];
    const float* gru_wh    = (const float*)d_in[11];
    const float* gru_bi    = (const float*)d_in[12];
    const float* gru_bh    = (const float*)d_in[13];
    const float* phi_w     = (const float*)d_in[14];
    const float* phi_b     = (const float*)d_in[15];
    const float* fc2_w     = (const float*)d_in[16];
    const float* fc2_b     = (const float*)d_in[17];
    float* out = (float*)d_out;

    static int smem_set = 0;
    if (!smem_set) {
        cudaFuncSetAttribute(k_main, cudaFuncAttributeMaxDynamicSharedMemorySize,
                             SMEM_BYTES);
        smem_set = 1;
    }

    k_wprep<<<513, 256>>>(hyp_w1, hyp_b1, hyp_w2, hyp_b2, merger_w,
                          gru_wi, gru_wh);
    k_main<<<BS/ROWS, 128, SMEM_BYTES>>>(in, hidden, fc1_w, fc1_b, gru_bi, gru_bh,
                                         rqs, phi_w, phi_b, fc2_w, fc2_b, out);
}